// round 2
// baseline (speedup 1.0000x reference)
#include <cuda_runtime.h>
#include <math_constants.h>

#define N_NODES 100000
#define N_EDGES 1600000
#define IN_F 128
#define HID 64
#define OUT_F 64
#define NEG_SLOPE 0.2f
#define E_TOT (N_EDGES + N_NODES)

// ---------------- scratch (device globals; no allocation allowed) ----------
__device__ float g_h[N_NODES * HID];     // h = x @ W
__device__ float g_agg[N_NODES * HID];   // un-normalized weighted aggregate
__device__ float g_asrc[N_NODES];
__device__ float g_adst[N_NODES];
__device__ float g_m[N_NODES];           // segment max
__device__ float g_denom[N_NODES];       // segment sum of exp
__device__ float g_colsum[HID];          // sum over nodes of relu(agg+bias)

// ---------------- init -----------------------------------------------------
__global__ void init_kernel() {
    int i = blockIdx.x * blockDim.x + threadIdx.x;
    if (i < N_NODES * HID) g_agg[i] = 0.f;
    if (i < N_NODES) { g_m[i] = -CUDART_INF_F; g_denom[i] = 0.f; }
    if (i < HID) g_colsum[i] = 0.f;
}

// ---------------- GEMM: h = x @ W  (64-row x 64-col tiles) -----------------
// smem: x tile 64x128 (pad 132) + W 128x64 (pad 68) = 68608 bytes dynamic
__global__ void gemm_kernel(const float* __restrict__ x, const float* __restrict__ W) {
    extern __shared__ float smem[];
    float* sx = smem;              // 64 * 132
    float* sw = smem + 64 * 132;   // 128 * 68
    int tid = threadIdx.x;
    int rb = blockIdx.x * 64;

    // load W (8192 floats) cooperatively, float4
    for (int i = tid; i < (IN_F * HID) / 4; i += 256) {
        int idx = i * 4;
        int k = idx >> 6, c = idx & 63;
        *(float4*)&sw[k * 68 + c] = *(const float4*)&W[idx];
    }
    // load x tile (64 x 128), float4, zero-fill out of range rows
    for (int i = tid; i < (64 * IN_F) / 4; i += 256) {
        int idx = i * 4;
        int r = idx >> 7, c = idx & 127;
        float4 v = make_float4(0.f, 0.f, 0.f, 0.f);
        if (rb + r < N_NODES) v = *(const float4*)&x[(size_t)(rb + r) * IN_F + c];
        *(float4*)&sx[r * 132 + c] = v;
    }
    __syncthreads();

    int tr = tid >> 4, tc = tid & 15;       // 16x16 threads, each 4 rows x 4 cols
    float acc[4][4] = {};
    #pragma unroll 8
    for (int k = 0; k < IN_F; k += 4) {
        float4 xr[4];
        #pragma unroll
        for (int i = 0; i < 4; i++)
            xr[i] = *(float4*)&sx[(tr * 4 + i) * 132 + k];
        #pragma unroll
        for (int kk = 0; kk < 4; kk++) {
            float4 wv = *(float4*)&sw[(k + kk) * 68 + tc * 4];
            #pragma unroll
            for (int i = 0; i < 4; i++) {
                float xv = (kk == 0) ? xr[i].x : (kk == 1) ? xr[i].y : (kk == 2) ? xr[i].z : xr[i].w;
                acc[i][0] += xv * wv.x;
                acc[i][1] += xv * wv.y;
                acc[i][2] += xv * wv.z;
                acc[i][3] += xv * wv.w;
            }
        }
    }
    #pragma unroll
    for (int i = 0; i < 4; i++) {
        int r = rb + tr * 4 + i;
        if (r < N_NODES)
            *(float4*)&g_h[(size_t)r * HID + tc * 4] =
                make_float4(acc[i][0], acc[i][1], acc[i][2], acc[i][3]);
    }
}

// ---------------- per-node attention scores --------------------------------
__global__ void scores_kernel(const float* __restrict__ att_src,
                              const float* __restrict__ att_dst) {
    int gwarp = (blockIdx.x * blockDim.x + threadIdx.x) >> 5;
    int lane  = threadIdx.x & 31;
    int nwarp = (gridDim.x * blockDim.x) >> 5;
    float as0 = att_src[lane * 2], as1 = att_src[lane * 2 + 1];
    float ad0 = att_dst[lane * 2], ad1 = att_dst[lane * 2 + 1];
    for (int n = gwarp; n < N_NODES; n += nwarp) {
        float2 hv = *(const float2*)&g_h[(size_t)n * HID + lane * 2];
        float s = hv.x * as0 + hv.y * as1;
        float d = hv.x * ad0 + hv.y * ad1;
        #pragma unroll
        for (int o = 16; o; o >>= 1) {
            s += __shfl_xor_sync(0xffffffffu, s, o);
            d += __shfl_xor_sync(0xffffffffu, d, o);
        }
        if (lane == 0) { g_asrc[n] = s; g_adst[n] = d; }
    }
}

// ---------------- edge pass 1: segment max ---------------------------------
__device__ __forceinline__ void atomicMaxF(float* addr, float val) {
    if (val >= 0.f) atomicMax((int*)addr, __float_as_int(val));
    else            atomicMin((unsigned*)addr, __float_as_uint(val));
}

__global__ void max_kernel(const int* __restrict__ ei) {
    int e = blockIdx.x * blockDim.x + threadIdx.x;
    if (e >= E_TOT) return;
    int s, d;
    if (e < N_EDGES) { s = ei[e]; d = ei[N_EDGES + e]; }
    else             { s = d = e - N_EDGES; }
    float l = g_asrc[s] + g_adst[d];
    l = l > 0.f ? l : NEG_SLOPE * l;
    atomicMaxF(&g_m[d], l);
}

// ---------------- edge pass 2: exp, denom, weighted scatter ----------------
// warp per edge; 2 floats per lane; vector red.add.v2 into agg[dst]
__global__ void scatter_kernel(const int* __restrict__ ei) {
    int gw   = (blockIdx.x * blockDim.x + threadIdx.x) >> 5;
    int lane = threadIdx.x & 31;
    if (gw >= E_TOT) return;
    int s, d;
    if (gw < N_EDGES) { s = ei[gw]; d = ei[N_EDGES + gw]; }
    else              { s = d = gw - N_EDGES; }
    float l = g_asrc[s] + g_adst[d];
    l = l > 0.f ? l : NEG_SLOPE * l;
    float ev = __expf(l - g_m[d]);
    if (lane == 0) atomicAdd(&g_denom[d], ev);
    float2 hv = *(const float2*)&g_h[(size_t)s * HID + lane * 2];
    float* dst = &g_agg[(size_t)d * HID + lane * 2];
    asm volatile("red.global.add.v2.f32 [%0], {%1, %2};"
                 :: "l"(dst), "f"(hv.x * ev), "f"(hv.y * ev) : "memory");
}

// ---------------- node pass: normalize, +bias, relu, column sum ------------
__global__ void nodered_kernel(const float* __restrict__ bias) {
    int c   = threadIdx.x & 63;   // column
    int sub = threadIdx.x >> 6;   // 0..3 node-lanes
    float b = bias[c];
    float acc = 0.f;
    int stride = gridDim.x * 4;
    for (int n = blockIdx.x * 4 + sub; n < N_NODES; n += stride) {
        float v = g_agg[(size_t)n * HID + c] / g_denom[n] + b;
        acc += v > 0.f ? v : 0.f;
    }
    __shared__ float red[256];
    red[threadIdx.x] = acc;
    __syncthreads();
    if (sub == 0) {
        float t = red[c] + red[64 + c] + red[128 + c] + red[192 + c];
        atomicAdd(&g_colsum[c], t);
    }
}

// ---------------- final: mean @ W_lin + b_lin ------------------------------
__global__ void final_kernel(const float* __restrict__ W_lin,
                             const float* __restrict__ b_lin,
                             float* __restrict__ out) {
    int c = threadIdx.x;  // 64 threads
    float acc = b_lin[c];
    const float inv_n = 1.0f / (float)N_NODES;
    #pragma unroll 8
    for (int k = 0; k < HID; k++)
        acc += (g_colsum[k] * inv_n) * W_lin[k * OUT_F + c];
    out[c] = acc;
}

// ---------------- launch ----------------------------------------------------
extern "C" void kernel_launch(void* const* d_in, const int* in_sizes, int n_in,
                              void* d_out, int out_size) {
    const float* x       = (const float*)d_in[0];
    const int*   ei      = (const int*)d_in[1];     // int32! (JAX x64 disabled)
    const float* W       = (const float*)d_in[2];
    const float* att_src = (const float*)d_in[3];
    const float* att_dst = (const float*)d_in[4];
    const float* bias    = (const float*)d_in[5];
    const float* W_lin   = (const float*)d_in[6];
    const float* b_lin   = (const float*)d_in[7];
    float*       out     = (float*)d_out;

    static bool attr_set = false;
    if (!attr_set) {
        cudaFuncSetAttribute(gemm_kernel,
                             cudaFuncAttributeMaxDynamicSharedMemorySize, 68608);
        attr_set = true;
    }

    init_kernel<<<(N_NODES * HID + 255) / 256, 256>>>();
    gemm_kernel<<<(N_NODES + 63) / 64, 256, 68608>>>(x, W);
    scores_kernel<<<592, 256>>>(att_src, att_dst);
    max_kernel<<<(E_TOT + 255) / 256, 256>>>(ei);
    scatter_kernel<<<(E_TOT + 7) / 8, 256>>>(ei);
    nodered_kernel<<<592, 256>>>(bias);
    final_kernel<<<1, 64>>>(W_lin, b_lin, out);
}

// round 4
// speedup vs baseline: 1.8715x; 1.8715x over previous
#include <cuda_runtime.h>

#define N_NODES 100000
#define N_EDGES 1600000
#define IN_F 128
#define HID 64
#define OUT_F 64
#define NEG_SLOPE 0.2f
#define E_TOT (N_EDGES + N_NODES)

#define SCAN_BLK 256
#define NBLK ((N_NODES + SCAN_BLK - 1) / SCAN_BLK)   // 391

// ---------------- scratch (device globals; no allocation allowed) ----------
__device__ float g_h[N_NODES * HID];       // h = x @ W
__device__ float g_asrc[N_NODES];
__device__ float g_adst[N_NODES];
__device__ int   g_cnt[N_NODES];           // in-degree histogram
__device__ int   g_rowstart[N_NODES + 1];  // CSR offsets
__device__ int   g_cursor[N_NODES];        // working copy for fill
__device__ int   g_blksum[NBLK];           // per-block sums for 2-level scan
__device__ int   g_csr_src[E_TOT];         // src node per CSR slot
__device__ float g_csr_e[E_TOT];           // exp(leaky(logit)) per CSR slot
__device__ float g_colsum[HID];            // sum over nodes of relu(out)

// ---------------- init: zero histogram + colsum ----------------------------
__global__ void init_kernel() {
    int i = blockIdx.x * blockDim.x + threadIdx.x;
    if (i < N_NODES) g_cnt[i] = 0;
    if (i < HID) g_colsum[i] = 0.f;
}

// ---------------- GEMM: h = x @ W, fused per-node attention scores ---------
// smem: x tile 64x128 (pad 132) + W 128x64 (pad 68) = 68608 bytes dynamic
__global__ void gemm_kernel(const float* __restrict__ x, const float* __restrict__ W,
                            const float* __restrict__ att_src,
                            const float* __restrict__ att_dst) {
    extern __shared__ float smem[];
    float* sx = smem;              // 64 * 132
    float* sw = smem + 64 * 132;   // 128 * 68
    int tid = threadIdx.x;
    int rb = blockIdx.x * 64;

    for (int i = tid; i < (IN_F * HID) / 4; i += 256) {
        int idx = i * 4;
        int k = idx >> 6, c = idx & 63;
        *(float4*)&sw[k * 68 + c] = *(const float4*)&W[idx];
    }
    for (int i = tid; i < (64 * IN_F) / 4; i += 256) {
        int idx = i * 4;
        int r = idx >> 7, c = idx & 127;
        float4 v = make_float4(0.f, 0.f, 0.f, 0.f);
        if (rb + r < N_NODES) v = *(const float4*)&x[(size_t)(rb + r) * IN_F + c];
        *(float4*)&sx[r * 132 + c] = v;
    }
    __syncthreads();

    int tr = tid >> 4, tc = tid & 15;       // 16x16 threads, each 4 rows x 4 cols
    float acc[4][4] = {};
    #pragma unroll 8
    for (int k = 0; k < IN_F; k += 4) {
        float4 xr[4];
        #pragma unroll
        for (int i = 0; i < 4; i++)
            xr[i] = *(float4*)&sx[(tr * 4 + i) * 132 + k];
        #pragma unroll
        for (int kk = 0; kk < 4; kk++) {
            float4 wv = *(float4*)&sw[(k + kk) * 68 + tc * 4];
            #pragma unroll
            for (int i = 0; i < 4; i++) {
                float xv = (kk == 0) ? xr[i].x : (kk == 1) ? xr[i].y : (kk == 2) ? xr[i].z : xr[i].w;
                acc[i][0] += xv * wv.x;
                acc[i][1] += xv * wv.y;
                acc[i][2] += xv * wv.z;
                acc[i][3] += xv * wv.w;
            }
        }
    }
    // write h
    #pragma unroll
    for (int i = 0; i < 4; i++) {
        int r = rb + tr * 4 + i;
        if (r < N_NODES)
            *(float4*)&g_h[(size_t)r * HID + tc * 4] =
                make_float4(acc[i][0], acc[i][1], acc[i][2], acc[i][3]);
    }
    // fused scores: a_src[r] = h[r]·att_src, a_dst[r] = h[r]·att_dst
    float as[4], ad[4];
    #pragma unroll
    for (int j = 0; j < 4; j++) {
        as[j] = __ldg(&att_src[tc * 4 + j]);
        ad[j] = __ldg(&att_dst[tc * 4 + j]);
    }
    #pragma unroll
    for (int i = 0; i < 4; i++) {
        float ps = 0.f, pd = 0.f;
        #pragma unroll
        for (int j = 0; j < 4; j++) { ps += acc[i][j] * as[j]; pd += acc[i][j] * ad[j]; }
        #pragma unroll
        for (int off = 8; off; off >>= 1) {
            ps += __shfl_xor_sync(0xffffffffu, ps, off);
            pd += __shfl_xor_sync(0xffffffffu, pd, off);
        }
        int r = rb + tr * 4 + i;
        if (tc == 0 && r < N_NODES) { g_asrc[r] = ps; g_adst[r] = pd; }
    }
}

// ---------------- histogram of destination degrees -------------------------
__global__ void hist_kernel(const int* __restrict__ ei) {
    int e = blockIdx.x * blockDim.x + threadIdx.x;
    if (e >= E_TOT) return;
    int d = (e < N_EDGES) ? ei[N_EDGES + e] : (e - N_EDGES);
    atomicAdd(&g_cnt[d], 1);
}

// ---------------- 2-level exclusive scan -----------------------------------
// pass 1: per-block inclusive scan of g_cnt -> rowstart (shifted later),
//         block total -> g_blksum
__global__ void scan1_kernel() {
    __shared__ int s[SCAN_BLK];
    int t = threadIdx.x;
    int i = blockIdx.x * SCAN_BLK + t;
    int v = (i < N_NODES) ? g_cnt[i] : 0;
    s[t] = v;
    __syncthreads();
    for (int off = 1; off < SCAN_BLK; off <<= 1) {
        int u = (t >= off) ? s[t - off] : 0;
        __syncthreads();
        s[t] += u;
        __syncthreads();
    }
    if (i < N_NODES) g_rowstart[i + 1 == N_NODES + 1 ? N_NODES : i + 1] = 0; // no-op placeholder
    if (i < N_NODES) g_cursor[i] = s[t] - v;   // exclusive within block (temp)
    if (t == SCAN_BLK - 1) g_blksum[blockIdx.x] = s[t];
}

// pass 2: scan of block sums (one block, NBLK <= 512)
__global__ void scan2_kernel() {
    __shared__ int s[512];
    int t = threadIdx.x;
    int v = (t < NBLK) ? g_blksum[t] : 0;
    s[t] = v;
    __syncthreads();
    for (int off = 1; off < 512; off <<= 1) {
        int u = (t >= off) ? s[t - off] : 0;
        __syncthreads();
        s[t] += u;
        __syncthreads();
    }
    if (t < NBLK) g_blksum[t] = s[t] - v;   // exclusive block offsets
}

// pass 3: add block offsets -> final rowstart & cursor
__global__ void scan3_kernel() {
    int i = blockIdx.x * SCAN_BLK + threadIdx.x;
    if (i >= N_NODES) return;
    int r = g_cursor[i] + g_blksum[blockIdx.x];
    g_rowstart[i] = r;
    g_cursor[i] = r;
    if (i == N_NODES - 1) g_rowstart[N_NODES] = E_TOT;
}

// ---------------- fill CSR: src id + per-edge exp weight -------------------
__global__ void fill_kernel(const int* __restrict__ ei) {
    int e = blockIdx.x * blockDim.x + threadIdx.x;
    if (e >= E_TOT) return;
    int s, d;
    if (e < N_EDGES) { s = ei[e]; d = ei[N_EDGES + e]; }
    else             { s = d = e - N_EDGES; }
    float l = g_asrc[s] + g_adst[d];
    l = l > 0.f ? l : NEG_SLOPE * l;
    int p = atomicAdd(&g_cursor[d], 1);
    g_csr_src[p] = s;
    g_csr_e[p] = __expf(l);           // no max-shift: logits bounded ~|8|
}

// ---------------- aggregate: warp per dst node, register accumulation ------
// also fused: normalize, +bias, relu, column-sum into g_colsum
__global__ void agg_kernel(const float* __restrict__ bias) {
    int lane  = threadIdx.x & 31;
    int gwarp = (blockIdx.x * blockDim.x + threadIdx.x) >> 5;
    int nwarp = (gridDim.x * blockDim.x) >> 5;
    int c0 = lane * 2;
    float b0 = bias[c0], b1 = bias[c0 + 1];
    float rs0 = 0.f, rs1 = 0.f;   // per-thread running column sums

    for (int n = gwarp; n < N_NODES; n += nwarp) {
        int beg = g_rowstart[n];
        int end = g_rowstart[n + 1];
        float acc0 = 0.f, acc1 = 0.f, den = 0.f;
        #pragma unroll 4
        for (int j = beg; j < end; j++) {
            int s   = g_csr_src[j];     // warp-broadcast load
            float e = g_csr_e[j];       // warp-broadcast load
            float2 hv = *(const float2*)&g_h[(size_t)s * HID + c0];
            acc0 += e * hv.x;
            acc1 += e * hv.y;
            den  += e;
        }
        float inv = __fdividef(1.f, den);
        float v0 = acc0 * inv + b0;
        float v1 = acc1 * inv + b1;
        rs0 += v0 > 0.f ? v0 : 0.f;
        rs1 += v1 > 0.f ? v1 : 0.f;
    }

    // block reduce per column then one global atomic per column
    __shared__ float scol[8][64];       // 8 warps per 256-thread block
    int w = threadIdx.x >> 5;
    scol[w][c0] = rs0;
    scol[w][c0 + 1] = rs1;
    __syncthreads();
    if (threadIdx.x < 64) {
        float t = 0.f;
        #pragma unroll
        for (int i = 0; i < 8; i++) t += scol[i][threadIdx.x];
        atomicAdd(&g_colsum[threadIdx.x], t);
    }
}

// ---------------- final: mean @ W_lin + b_lin ------------------------------
__global__ void final_kernel(const float* __restrict__ W_lin,
                             const float* __restrict__ b_lin,
                             float* __restrict__ out) {
    int c = threadIdx.x;  // 64 threads
    float acc = b_lin[c];
    const float inv_n = 1.0f / (float)N_NODES;
    #pragma unroll 8
    for (int k = 0; k < HID; k++)
        acc += (g_colsum[k] * inv_n) * W_lin[k * OUT_F + c];
    out[c] = acc;
}

// ---------------- launch ----------------------------------------------------
extern "C" void kernel_launch(void* const* d_in, const int* in_sizes, int n_in,
                              void* d_out, int out_size) {
    const float* x       = (const float*)d_in[0];
    const int*   ei      = (const int*)d_in[1];     // int32 (JAX x64 disabled)
    const float* W       = (const float*)d_in[2];
    const float* att_src = (const float*)d_in[3];
    const float* att_dst = (const float*)d_in[4];
    const float* bias    = (const float*)d_in[5];
    const float* W_lin   = (const float*)d_in[6];
    const float* b_lin   = (const float*)d_in[7];
    float*       out     = (float*)d_out;

    static bool attr_set = false;
    if (!attr_set) {
        cudaFuncSetAttribute(gemm_kernel,
                             cudaFuncAttributeMaxDynamicSharedMemorySize, 68608);
        attr_set = true;
    }

    init_kernel<<<(N_NODES + 255) / 256, 256>>>();
    gemm_kernel<<<(N_NODES + 63) / 64, 256, 68608>>>(x, W, att_src, att_dst);
    hist_kernel<<<(E_TOT + 255) / 256, 256>>>(ei);
    scan1_kernel<<<NBLK, SCAN_BLK>>>();
    scan2_kernel<<<1, 512>>>();
    scan3_kernel<<<NBLK, SCAN_BLK>>>();
    fill_kernel<<<(E_TOT + 255) / 256, 256>>>(ei);
    agg_kernel<<<1184, 256>>>(bias);
    final_kernel<<<1, 64>>>(W_lin, b_lin, out);
}

// round 6
// speedup vs baseline: 2.2064x; 1.1789x over previous
#include <cuda_runtime.h>
#include <cuda_bf16.h>

#define N_NODES 100000
#define N_EDGES 1600000
#define IN_F 128
#define HID 64
#define OUT_F 64
#define NEG_SLOPE 0.2f
#define E_TOT (N_EDGES + N_NODES)

#define SCAN_BLK 256
#define NBLK ((N_NODES + SCAN_BLK - 1) / SCAN_BLK)   // 391

// ---------------- scratch (device globals; no allocation allowed) ----------
__device__ __nv_bfloat162 g_hb[N_NODES * 32];  // h in bf16, 64 cols = 32 bf162
__device__ float g_asrc[N_NODES];
__device__ float g_adst[N_NODES];
__device__ int   g_cnt[N_NODES];               // in-degree histogram
__device__ int   g_rowstart[N_NODES + 1];      // CSR offsets
__device__ int   g_cursor[N_NODES];            // working copy for fill
__device__ int   g_blksum[NBLK];               // block sums for 2-level scan
__device__ int2  g_csr[E_TOT];                 // {src, exp-bits} per CSR slot
__device__ float g_colsum[HID];                // sum over nodes of relu(out)

// ---------------- init ------------------------------------------------------
__global__ void init_kernel() {
    int i = blockIdx.x * blockDim.x + threadIdx.x;
    if (i < N_NODES) g_cnt[i] = 0;
    if (i < HID) g_colsum[i] = 0.f;
}

// ---------------- tf32 helper ----------------------------------------------
__device__ __forceinline__ float to_tf32(float f) {
    unsigned u;
    asm("cvt.rna.tf32.f32 %0, %1;" : "=r"(u) : "f"(f));
    return __uint_as_float(u);
}

// ---------------- GEMM (tf32 mma): h = x @ W, fused scores, bf16 h out -----
// block: 256 thr (8 warps), 128 rows; warp = 16 rows x 64 cols
// smem: sx 128x132 fp32(tf32 bits) + sw 128x68 = 102400 B dynamic
__global__ void gemm_kernel(const float* __restrict__ x, const float* __restrict__ W,
                            const float* __restrict__ att_src,
                            const float* __restrict__ att_dst) {
    extern __shared__ float smem[];
    float* sx = smem;               // 128 * 132
    float* sw = smem + 128 * 132;   // 128 * 68
    int tid = threadIdx.x;
    int rb = blockIdx.x * 128;

    // load W (128x64) -> tf32 bits in smem
    for (int i = tid; i < (IN_F * HID) / 4; i += 256) {
        int idx = i * 4;
        int k = idx >> 6, c = idx & 63;
        float4 v = *(const float4*)&W[idx];
        v.x = to_tf32(v.x); v.y = to_tf32(v.y); v.z = to_tf32(v.z); v.w = to_tf32(v.w);
        *(float4*)&sw[k * 68 + c] = v;
    }
    // load x tile (128x128) -> tf32 bits in smem (zero-fill OOB rows)
    for (int i = tid; i < (128 * IN_F) / 4; i += 256) {
        int idx = i * 4;
        int r = idx >> 7, c = idx & 127;
        float4 v = make_float4(0.f, 0.f, 0.f, 0.f);
        if (rb + r < N_NODES) {
            v = *(const float4*)&x[(size_t)(rb + r) * IN_F + c];
            v.x = to_tf32(v.x); v.y = to_tf32(v.y); v.z = to_tf32(v.z); v.w = to_tf32(v.w);
        }
        *(float4*)&sx[r * 132 + c] = v;
    }
    __syncthreads();

    int warp = tid >> 5, lane = tid & 31;
    int gid = lane >> 2, tig = lane & 3;
    int wr0 = warp * 16;

    float c[8][4];
    #pragma unroll
    for (int t = 0; t < 8; t++) { c[t][0] = c[t][1] = c[t][2] = c[t][3] = 0.f; }

    #pragma unroll 4
    for (int ks = 0; ks < 16; ks++) {
        int k0 = ks * 8;
        unsigned a0 = __float_as_uint(sx[(wr0 + gid)     * 132 + k0 + tig]);
        unsigned a1 = __float_as_uint(sx[(wr0 + gid + 8) * 132 + k0 + tig]);
        unsigned a2 = __float_as_uint(sx[(wr0 + gid)     * 132 + k0 + tig + 4]);
        unsigned a3 = __float_as_uint(sx[(wr0 + gid + 8) * 132 + k0 + tig + 4]);
        #pragma unroll
        for (int t = 0; t < 8; t++) {
            unsigned b0 = __float_as_uint(sw[(k0 + tig)     * 68 + t * 8 + gid]);
            unsigned b1 = __float_as_uint(sw[(k0 + tig + 4) * 68 + t * 8 + gid]);
            asm("mma.sync.aligned.m16n8k8.row.col.f32.tf32.tf32.f32 "
                "{%0,%1,%2,%3}, {%4,%5,%6,%7}, {%8,%9}, {%0,%1,%2,%3};"
                : "+f"(c[t][0]), "+f"(c[t][1]), "+f"(c[t][2]), "+f"(c[t][3])
                : "r"(a0), "r"(a1), "r"(a2), "r"(a3), "r"(b0), "r"(b1));
        }
    }

    int rA = rb + wr0 + gid;       // this thread's two output rows
    int rB = rA + 8;

    // fused scores over this thread's 16 cols (tile t: cols t*8+2tig, +1)
    float psA = 0.f, pdA = 0.f, psB = 0.f, pdB = 0.f;
    #pragma unroll
    for (int t = 0; t < 8; t++) {
        int cc = t * 8 + 2 * tig;
        float s0 = __ldg(&att_src[cc]),     s1 = __ldg(&att_src[cc + 1]);
        float d0 = __ldg(&att_dst[cc]),     d1 = __ldg(&att_dst[cc + 1]);
        psA += c[t][0] * s0 + c[t][1] * s1;
        pdA += c[t][0] * d0 + c[t][1] * d1;
        psB += c[t][2] * s0 + c[t][3] * s1;
        pdB += c[t][2] * d0 + c[t][3] * d1;
    }
    #pragma unroll
    for (int off = 1; off <= 2; off <<= 1) {
        psA += __shfl_xor_sync(0xffffffffu, psA, off);
        pdA += __shfl_xor_sync(0xffffffffu, pdA, off);
        psB += __shfl_xor_sync(0xffffffffu, psB, off);
        pdB += __shfl_xor_sync(0xffffffffu, pdB, off);
    }
    if (tig == 0) {
        if (rA < N_NODES) { g_asrc[rA] = psA; g_adst[rA] = pdA; }
        if (rB < N_NODES) { g_asrc[rB] = psB; g_adst[rB] = pdB; }
    }

    // store h as bf16 (cols t*8+2tig -> bf162 index t*4+tig)
    #pragma unroll
    for (int t = 0; t < 8; t++) {
        if (rA < N_NODES)
            g_hb[(size_t)rA * 32 + t * 4 + tig] = __floats2bfloat162_rn(c[t][0], c[t][1]);
        if (rB < N_NODES)
            g_hb[(size_t)rB * 32 + t * 4 + tig] = __floats2bfloat162_rn(c[t][2], c[t][3]);
    }
}

// ---------------- histogram of destination degrees -------------------------
__global__ void hist_kernel(const int* __restrict__ ei) {
    int e = blockIdx.x * blockDim.x + threadIdx.x;
    if (e >= E_TOT) return;
    int d = (e < N_EDGES) ? ei[N_EDGES + e] : (e - N_EDGES);
    atomicAdd(&g_cnt[d], 1);
}

// ---------------- 2-level exclusive scan -----------------------------------
__global__ void scan1_kernel() {
    __shared__ int s[SCAN_BLK];
    int t = threadIdx.x;
    int i = blockIdx.x * SCAN_BLK + t;
    int v = (i < N_NODES) ? g_cnt[i] : 0;
    s[t] = v;
    __syncthreads();
    for (int off = 1; off < SCAN_BLK; off <<= 1) {
        int u = (t >= off) ? s[t - off] : 0;
        __syncthreads();
        s[t] += u;
        __syncthreads();
    }
    if (i < N_NODES) g_cursor[i] = s[t] - v;   // exclusive within block (temp)
    if (t == SCAN_BLK - 1) g_blksum[blockIdx.x] = s[t];
}

__global__ void scan2_kernel() {
    __shared__ int s[512];
    int t = threadIdx.x;
    int v = (t < NBLK) ? g_blksum[t] : 0;
    s[t] = v;
    __syncthreads();
    for (int off = 1; off < 512; off <<= 1) {
        int u = (t >= off) ? s[t - off] : 0;
        __syncthreads();
        s[t] += u;
        __syncthreads();
    }
    if (t < NBLK) g_blksum[t] = s[t] - v;      // exclusive block offsets
}

__global__ void scan3_kernel() {
    int i = blockIdx.x * SCAN_BLK + threadIdx.x;
    if (i >= N_NODES) return;
    int r = g_cursor[i] + g_blksum[blockIdx.x];
    g_rowstart[i] = r;
    g_cursor[i] = r;
    if (i == N_NODES - 1) g_rowstart[N_NODES] = E_TOT;
}

// ---------------- fill CSR: single 8B scattered store per edge -------------
__global__ void fill_kernel(const int* __restrict__ ei) {
    int e = blockIdx.x * blockDim.x + threadIdx.x;
    if (e >= E_TOT) return;
    int s, d;
    if (e < N_EDGES) { s = ei[e]; d = ei[N_EDGES + e]; }
    else             { s = d = e - N_EDGES; }
    float l = g_asrc[s] + g_adst[d];
    l = l > 0.f ? l : NEG_SLOPE * l;
    int p = atomicAdd(&g_cursor[d], 1);
    g_csr[p] = make_int2(s, __float_as_int(__expf(l)));  // logits bounded ~|8|
}

// ---------------- aggregate: warp per dst node, bf16 h gather --------------
// fused: normalize, +bias, relu, column-sum into g_colsum
__global__ void agg_kernel(const float* __restrict__ bias) {
    int lane  = threadIdx.x & 31;
    int gwarp = (blockIdx.x * blockDim.x + threadIdx.x) >> 5;
    int nwarp = (gridDim.x * blockDim.x) >> 5;
    int c0 = lane * 2;
    float b0 = bias[c0], b1 = bias[c0 + 1];
    float rs0 = 0.f, rs1 = 0.f;

    for (int n = gwarp; n < N_NODES; n += nwarp) {
        int beg = g_rowstart[n];
        int end = g_rowstart[n + 1];
        float acc0 = 0.f, acc1 = 0.f, den = 0.f;
        #pragma unroll 4
        for (int j = beg; j < end; j++) {
            int2 v = g_csr[j];                         // warp-broadcast 8B
            float e = __int_as_float(v.y);
            float2 hf = __bfloat1622float2(g_hb[(size_t)v.x * 32 + lane]);
            acc0 += e * hf.x;
            acc1 += e * hf.y;
            den  += e;
        }
        float inv = __fdividef(1.f, den);
        float v0 = acc0 * inv + b0;
        float v1 = acc1 * inv + b1;
        rs0 += v0 > 0.f ? v0 : 0.f;
        rs1 += v1 > 0.f ? v1 : 0.f;
    }

    __shared__ float scol[8][64];
    int w = threadIdx.x >> 5;
    scol[w][c0] = rs0;
    scol[w][c0 + 1] = rs1;
    __syncthreads();
    if (threadIdx.x < 64) {
        float t = 0.f;
        #pragma unroll
        for (int i = 0; i < 8; i++) t += scol[i][threadIdx.x];
        atomicAdd(&g_colsum[threadIdx.x], t);
    }
}

// ---------------- final: mean @ W_lin + b_lin ------------------------------
__global__ void final_kernel(const float* __restrict__ W_lin,
                             const float* __restrict__ b_lin,
                             float* __restrict__ out) {
    int c = threadIdx.x;  // 64 threads
    float acc = b_lin[c];
    const float inv_n = 1.0f / (float)N_NODES;
    #pragma unroll 8
    for (int k = 0; k < HID; k++)
        acc += (g_colsum[k] * inv_n) * W_lin[k * OUT_F + c];
    out[c] = acc;
}

// ---------------- launch ----------------------------------------------------
extern "C" void kernel_launch(void* const* d_in, const int* in_sizes, int n_in,
                              void* d_out, int out_size) {
    const float* x       = (const float*)d_in[0];
    const int*   ei      = (const int*)d_in[1];     // int32 (JAX x64 disabled)
    const float* W       = (const float*)d_in[2];
    const float* att_src = (const float*)d_in[3];
    const float* att_dst = (const float*)d_in[4];
    const float* bias    = (const float*)d_in[5];
    const float* W_lin   = (const float*)d_in[6];
    const float* b_lin   = (const float*)d_in[7];
    float*       out     = (float*)d_out;

    static bool attr_set = false;
    if (!attr_set) {
        cudaFuncSetAttribute(gemm_kernel,
                             cudaFuncAttributeMaxDynamicSharedMemorySize, 102400);
        attr_set = true;
    }

    init_kernel<<<(N_NODES + 255) / 256, 256>>>();
    gemm_kernel<<<(N_NODES + 127) / 128, 256, 102400>>>(x, W, att_src, att_dst);
    hist_kernel<<<(E_TOT + 255) / 256, 256>>>(ei);
    scan1_kernel<<<NBLK, SCAN_BLK>>>();
    scan2_kernel<<<1, 512>>>();
    scan3_kernel<<<NBLK, SCAN_BLK>>>();
    fill_kernel<<<(E_TOT + 255) / 256, 256>>>(ei);
    agg_kernel<<<1184, 256>>>(bias);
    final_kernel<<<1, 64>>>(W_lin, b_lin, out);
}